// round 12
// baseline (speedup 1.0000x reference)
#include <cuda_runtime.h>
#include <math.h>

// Problem constants (fixed by the dataset)
#define VOCAB   32000
#define NBL     128        // B*L
#define NK      64         // 8 heads x 8

// Main-kernel tiling: 128 threads, each owns 8 bl-rows x 8 vocab-cols
#define BM      128        // full bl dimension per CTA
#define BN      64         // vocab tile -> grid.x = 500
#define KC      8          // k chunk for bl-coefficient smem
#define NTHR    128

typedef unsigned long long u64;

// ---------------------------------------------------------------------------
// Packed f32x2 helpers
// ---------------------------------------------------------------------------
__device__ __forceinline__ u64 pk(float x, float y) {
    u64 r; asm("mov.b64 %0, {%1, %2};" : "=l"(r) : "f"(x), "f"(y)); return r;
}
__device__ __forceinline__ void upk(u64 a, float& x, float& y) {
    asm("mov.b64 {%0, %1}, %2;" : "=f"(x), "=f"(y) : "l"(a));
}
__device__ __forceinline__ u64 mul2(u64 a, u64 b) {
    u64 r; asm("mul.rn.f32x2 %0, %1, %2;" : "=l"(r) : "l"(a), "l"(b)); return r;
}
__device__ __forceinline__ u64 fma2(u64 a, u64 b, u64 c) {
    u64 r; asm("fma.rn.f32x2 %0, %1, %2, %3;" : "=l"(r) : "l"(a), "l"(b), "l"(c)); return r;
}
// Packed min via two scalar FMNMX on register halves (pk/upk fold to aliases)
__device__ __forceinline__ u64 minp(u64 a, u64 b) {
    float a0, a1, b0, b1;
    upk(a, a0, a1); upk(b, b0, b1);
    return pk(fminf(a0, b0), fminf(a1, b1));
}

// ---------------------------------------------------------------------------
// Device scratch: 2 factored coefficient planes
//   g_ce[k][bl] = cp * e^f       (cp = W[h]*a*cos(p - iph))
//   g_e2[k][bl] = e^{-2f}
// ---------------------------------------------------------------------------
__device__ __align__(16) float g_ce[NK * NBL];
__device__ __align__(16) float g_e2[NK * NBL];

__global__ void prep_bl(const float* __restrict__ freqs,
                        const float* __restrict__ amps,
                        const float* __restrict__ phases,
                        const float* __restrict__ iph,
                        const float* __restrict__ W) {
    int idx = blockIdx.x * 256 + threadIdx.x;   // idx = bl*NK + k
    int bl = idx >> 6, k = idx & 63;
    float cp = amps[idx] * cosf(phases[idx] - iph[k]) * W[k >> 3];
    float f  = freqs[idx];
    int o = k * NBL + bl;
    g_ce[o] = cp * expf(f);
    g_e2[o] = expf(-2.0f * f);
}

// ---------------------------------------------------------------------------
// Main: out[bl][v] = sum_k (cp*e^f) * min(e^-vp, e^-2f * e^vp) + bias
//  - vocab smem: [k][pair p] float4 = (em_2p, em_2p+1, ep_2p, ep_2p+1)
//  - bl smem: 2 scalar planes [KC][BM]
//  - register double-buffering across kl: prefetch kl+1 operands while
//    computing kl (grid-limited occupancy -> registers are free up to 168)
// ---------------------------------------------------------------------------
__global__ void __launch_bounds__(NTHR, 3)
main_kernel(float* __restrict__ out,
            const float* __restrict__ vp,
            const float* __restrict__ bptr) {
    extern __shared__ char sm[];
    float4* s_v  = (float4*)sm;                   // [NK][32] pairs   32KB
    float*  s_ce = (float*)(sm + NK * 32 * 16);   // [KC][BM]          4KB
    float*  s_e2 = s_ce + KC * BM;                //                   4KB

    const int tid   = threadIdx.x;
    const int vbase = blockIdx.x * BN;

    // --- In-kernel vocab exp fill: 2048 (pair,k) items, 16 per thread ---
    #pragma unroll
    for (int it = 0; it < 16; ++it) {
        int idx = it * NTHR + tid;          // lanes sweep k -> coalesced LDG
        int p = idx >> 6;                   // 0..31
        int k = idx & 63;
        long a = (long)(vbase + 2 * p) * NK + k;
        float x0 = vp[a];
        float x1 = vp[a + NK];
        s_v[k * 32 + p] = make_float4(__expf(-x0), __expf(-x1),
                                      __expf(x0),  __expf(x1));
    }

    const int c  = tid & 7;                 // vocab pair group
    const int rg = tid >> 3;                // bl row-group: rows 8*rg..8*rg+7

    const float bias = bptr[0];
    const u64 bias2 = pk(bias, bias);
    u64 acc[8][4];
    #pragma unroll
    for (int i = 0; i < 8; ++i)
        #pragma unroll
        for (int j = 0; j < 4; ++j) acc[i][j] = bias2;   // bias folded into init

    for (int kc = 0; kc < NK; kc += KC) {
        // --- bl chunk fill: 2 planes x 256 float4, coalesced (2 iters) ---
        const float4* gc = (const float4*)(g_ce + kc * NBL);
        const float4* ge = (const float4*)(g_e2 + kc * NBL);
        #pragma unroll
        for (int it = 0; it < (KC * BM / 4) / NTHR; ++it) {
            int idx = it * NTHR + tid;
            ((float4*)s_ce)[idx] = gc[idx];
            ((float4*)s_e2)[idx] = ge[idx];
        }
        __syncthreads();   // also covers the vocab fill on the first chunk

        // --- software-pipelined kl loop: prefetch kl+1 while computing kl ---
        const ulonglong2* vvb = (const ulonglong2*)s_v + kc * 32 + c;

        // prologue: operands for kl = 0
        ulonglong2 q0 = vvb[0], q1 = vvb[8], q2 = vvb[16], q3 = vvb[24];
        float4 ce0 = ((const float4*)s_ce)[2 * rg];
        float4 ce1 = ((const float4*)s_ce)[2 * rg + 1];
        float4 e20 = ((const float4*)s_e2)[2 * rg];
        float4 e21 = ((const float4*)s_e2)[2 * rg + 1];

        #pragma unroll
        for (int kl = 0; kl < KC; ++kl) {
            ulonglong2 nq0, nq1, nq2, nq3;
            float4 nce0, nce1, ne20, ne21;
            if (kl + 1 < KC) {
                const ulonglong2* vv = vvb + (kl + 1) * 32;
                nq0 = vv[0]; nq1 = vv[8]; nq2 = vv[16]; nq3 = vv[24];
                const float4* pce = (const float4*)(s_ce + (kl + 1) * BM) + 2 * rg;
                const float4* pe2 = (const float4*)(s_e2 + (kl + 1) * BM) + 2 * rg;
                nce0 = pce[0]; nce1 = pce[1];
                ne20 = pe2[0]; ne21 = pe2[1];
            }

            #pragma unroll
            for (int i = 0; i < 8; ++i) {
                float cs = (i < 4) ? ((const float*)&ce0)[i] : ((const float*)&ce1)[i - 4];
                float es = (i < 4) ? ((const float*)&e20)[i] : ((const float*)&e21)[i - 4];
                u64 ced = pk(cs, cs);
                u64 e2d = pk(es, es);

                acc[i][0] = fma2(ced, minp(q0.x, mul2(e2d, q0.y)), acc[i][0]);
                acc[i][1] = fma2(ced, minp(q1.x, mul2(e2d, q1.y)), acc[i][1]);
                acc[i][2] = fma2(ced, minp(q2.x, mul2(e2d, q2.y)), acc[i][2]);
                acc[i][3] = fma2(ced, minp(q3.x, mul2(e2d, q3.y)), acc[i][3]);
            }

            if (kl + 1 < KC) {
                q0 = nq0; q1 = nq1; q2 = nq2; q3 = nq3;
                ce0 = nce0; ce1 = nce1; e20 = ne20; e21 = ne21;
            }
        }
        __syncthreads();
    }

    // --- Epilogue: 8 rows x 4 u64 pair-stores each (bias already in acc) ---
    #pragma unroll
    for (int i = 0; i < 8; ++i) {
        long rowbase = (long)(8 * rg + i) * VOCAB + vbase + 2 * c;
        #pragma unroll
        for (int j = 0; j < 4; ++j) {
            *(u64*)&out[rowbase + 16 * j] = acc[i][j];
        }
    }
}

// ---------------------------------------------------------------------------
extern "C" void kernel_launch(void* const* d_in, const int* in_sizes, int n_in,
                              void* d_out, int out_size) {
    const float* freqs  = (const float*)d_in[0];
    const float* amps   = (const float*)d_in[1];
    const float* phases = (const float*)d_in[2];
    const float* vp     = (const float*)d_in[3];
    const float* iph    = (const float*)d_in[4];
    const float* W      = (const float*)d_in[5];
    const float* b      = (const float*)d_in[6];
    float* out = (float*)d_out;

    prep_bl<<<(NBL * NK) / 256, 256>>>(freqs, amps, phases, iph, W);

    const int smem_bytes = NK * 32 * 16 + 2 * KC * BM * (int)sizeof(float);  // 36864
    cudaFuncSetAttribute(main_kernel, cudaFuncAttributeMaxDynamicSharedMemorySize, smem_bytes);
    cudaFuncSetAttribute(main_kernel, cudaFuncAttributePreferredSharedMemoryCarveout, 100);

    main_kernel<<<VOCAB / BN, NTHR, smem_bytes>>>(out, vp, b);
    (void)in_sizes; (void)n_in; (void)out_size;
}

// round 13
// speedup vs baseline: 1.0210x; 1.0210x over previous
#include <cuda_runtime.h>
#include <math.h>

// Problem constants (fixed by the dataset)
#define VOCAB   32000
#define NBL     128        // B*L
#define NK      64         // 8 heads x 8

// Main-kernel tiling: 64 threads, each owns 8 bl-rows x 8 vocab-cols
#define BM      128        // full bl dimension per CTA
#define BN      32         // vocab tile -> grid.x = 1000 (single wave @ 8 CTA/SM)
#define KC      8          // k chunk for bl-coefficient smem
#define NTHR    64

typedef unsigned long long u64;

// ---------------------------------------------------------------------------
// Packed f32x2 helpers
// ---------------------------------------------------------------------------
__device__ __forceinline__ u64 pk(float x, float y) {
    u64 r; asm("mov.b64 %0, {%1, %2};" : "=l"(r) : "f"(x), "f"(y)); return r;
}
__device__ __forceinline__ void upk(u64 a, float& x, float& y) {
    asm("mov.b64 {%0, %1}, %2;" : "=f"(x), "=f"(y) : "l"(a));
}
__device__ __forceinline__ u64 mul2(u64 a, u64 b) {
    u64 r; asm("mul.rn.f32x2 %0, %1, %2;" : "=l"(r) : "l"(a), "l"(b)); return r;
}
__device__ __forceinline__ u64 fma2(u64 a, u64 b, u64 c) {
    u64 r; asm("fma.rn.f32x2 %0, %1, %2, %3;" : "=l"(r) : "l"(a), "l"(b), "l"(c)); return r;
}
// Packed min via two scalar FMNMX on register halves (pk/upk fold to aliases)
__device__ __forceinline__ u64 minp(u64 a, u64 b) {
    float a0, a1, b0, b1;
    upk(a, a0, a1); upk(b, b0, b1);
    return pk(fminf(a0, b0), fminf(a1, b1));
}

// ---------------------------------------------------------------------------
// Device scratch: 2 factored coefficient planes
//   g_ce[k][bl] = cp * e^f       (cp = W[h]*a*cos(p - iph))
//   g_e2[k][bl] = e^{-2f}
// ---------------------------------------------------------------------------
__device__ __align__(16) float g_ce[NK * NBL];
__device__ __align__(16) float g_e2[NK * NBL];

__global__ void prep_bl(const float* __restrict__ freqs,
                        const float* __restrict__ amps,
                        const float* __restrict__ phases,
                        const float* __restrict__ iph,
                        const float* __restrict__ W) {
    int idx = blockIdx.x * 256 + threadIdx.x;   // idx = bl*NK + k
    int bl = idx >> 6, k = idx & 63;
    float cp = amps[idx] * cosf(phases[idx] - iph[k]) * W[k >> 3];
    float f  = freqs[idx];
    int o = k * NBL + bl;
    g_ce[o] = cp * expf(f);
    g_e2[o] = expf(-2.0f * f);
}

// ---------------------------------------------------------------------------
// Main: out[bl][v] = sum_k (cp*e^f) * min(e^-vp, e^-2f * e^vp) + bias
//  - vocab smem: [k][pair p] float4 = (em_2p, em_2p+1, ep_2p, ep_2p+1), 16 pairs
//    thread c in 0..3 reads pairs {c, c+4, c+8, c+12}
//  - bl smem: 2 scalar planes [KC][BM]; two LDS.128 per plane per kl (8 rows)
//  - 64-thr CTAs: grid 1000, 8 CTAs/SM by regs -> 16 warps/SM, single wave
// ---------------------------------------------------------------------------
__global__ void __launch_bounds__(NTHR, 8)
main_kernel(float* __restrict__ out,
            const float* __restrict__ vp,
            const float* __restrict__ bptr) {
    extern __shared__ char sm[];
    float4* s_v  = (float4*)sm;                   // [NK][16] pairs   16KB
    float*  s_ce = (float*)(sm + NK * 16 * 16);   // [KC][BM]          4KB
    float*  s_e2 = s_ce + KC * BM;                //                   4KB

    const int tid   = threadIdx.x;
    const int vbase = blockIdx.x * BN;

    // --- In-kernel vocab exp fill: 1024 (pair,k) items, 16 per thread ---
    #pragma unroll
    for (int it = 0; it < 16; ++it) {
        int idx = it * NTHR + tid;          // lanes sweep k -> coalesced LDG
        int p = idx >> 6;                   // 0..15
        int k = idx & 63;
        long a = (long)(vbase + 2 * p) * NK + k;
        float x0 = vp[a];
        float x1 = vp[a + NK];
        s_v[k * 16 + p] = make_float4(__expf(-x0), __expf(-x1),
                                      __expf(x0),  __expf(x1));
    }

    const int c  = tid & 3;                 // vocab pair group (4 groups)
    const int rg = tid >> 2;                // bl row-group: rows 8*rg..8*rg+7

    const float bias = bptr[0];
    const u64 bias2 = pk(bias, bias);
    u64 acc[8][4];
    #pragma unroll
    for (int i = 0; i < 8; ++i)
        #pragma unroll
        for (int j = 0; j < 4; ++j) acc[i][j] = bias2;   // bias folded into init

    for (int kc = 0; kc < NK; kc += KC) {
        // --- bl chunk fill: 2 planes x 256 float4, coalesced (4 iters) ---
        const float4* gc = (const float4*)(g_ce + kc * NBL);
        const float4* ge = (const float4*)(g_e2 + kc * NBL);
        #pragma unroll
        for (int it = 0; it < (KC * BM / 4) / NTHR; ++it) {
            int idx = it * NTHR + tid;
            ((float4*)s_ce)[idx] = gc[idx];
            ((float4*)s_e2)[idx] = ge[idx];
        }
        __syncthreads();   // also covers the vocab fill on the first chunk

        #pragma unroll
        for (int kl = 0; kl < KC; ++kl) {
            const ulonglong2* vv = (const ulonglong2*)s_v + (kc + kl) * 16 + c;
            ulonglong2 q0 = vv[0];     // .x=(em,em') .y=(ep,ep')
            ulonglong2 q1 = vv[4];
            ulonglong2 q2 = vv[8];
            ulonglong2 q3 = vv[12];

            // this thread's 8 rows: 2 LDS.128 per plane
            const float4* pce = (const float4*)(s_ce + kl * BM) + 2 * rg;
            const float4* pe2 = (const float4*)(s_e2 + kl * BM) + 2 * rg;
            float4 ce0 = pce[0], ce1 = pce[1];
            float4 e20 = pe2[0], e21 = pe2[1];

            #pragma unroll
            for (int i = 0; i < 8; ++i) {
                float cs = (i < 4) ? ((const float*)&ce0)[i] : ((const float*)&ce1)[i - 4];
                float es = (i < 4) ? ((const float*)&e20)[i] : ((const float*)&e21)[i - 4];
                u64 ced = pk(cs, cs);
                u64 e2d = pk(es, es);

                acc[i][0] = fma2(ced, minp(q0.x, mul2(e2d, q0.y)), acc[i][0]);
                acc[i][1] = fma2(ced, minp(q1.x, mul2(e2d, q1.y)), acc[i][1]);
                acc[i][2] = fma2(ced, minp(q2.x, mul2(e2d, q2.y)), acc[i][2]);
                acc[i][3] = fma2(ced, minp(q3.x, mul2(e2d, q3.y)), acc[i][3]);
            }
        }
        __syncthreads();
    }

    // --- Epilogue: 8 rows x 4 u64 pair-stores (bias already in acc) ---
    // columns for pair j: vbase + 2*c + 8*j
    #pragma unroll
    for (int i = 0; i < 8; ++i) {
        long rowbase = (long)(8 * rg + i) * VOCAB + vbase + 2 * c;
        #pragma unroll
        for (int j = 0; j < 4; ++j) {
            *(u64*)&out[rowbase + 8 * j] = acc[i][j];
        }
    }
}

// ---------------------------------------------------------------------------
extern "C" void kernel_launch(void* const* d_in, const int* in_sizes, int n_in,
                              void* d_out, int out_size) {
    const float* freqs  = (const float*)d_in[0];
    const float* amps   = (const float*)d_in[1];
    const float* phases = (const float*)d_in[2];
    const float* vp     = (const float*)d_in[3];
    const float* iph    = (const float*)d_in[4];
    const float* W      = (const float*)d_in[5];
    const float* b      = (const float*)d_in[6];
    float* out = (float*)d_out;

    prep_bl<<<(NBL * NK) / 256, 256>>>(freqs, amps, phases, iph, W);

    const int smem_bytes = NK * 16 * 16 + 2 * KC * BM * (int)sizeof(float);  // 24576
    cudaFuncSetAttribute(main_kernel, cudaFuncAttributeMaxDynamicSharedMemorySize, smem_bytes);
    cudaFuncSetAttribute(main_kernel, cudaFuncAttributePreferredSharedMemoryCarveout, 100);

    main_kernel<<<VOCAB / BN, NTHR, smem_bytes>>>(out, vp, b);
    (void)in_sizes; (void)n_in; (void)out_size;
}